// round 2
// baseline (speedup 1.0000x reference)
#include <cuda_runtime.h>

#define NN 100000
#define EE 600000
#define DD 128

// ---- device scratch (allocation-free rule: __device__ globals) ----
__device__ __align__(16) float g_h1w[(size_t)NN * DD];   // x @ W1
__device__ __align__(16) float g_agg1[(size_t)NN * DD];  // relu(aggregate + b1)
__device__ __align__(16) float2 g_h2w[NN];               // agg1 @ W2
__device__ int   g_cnt[NN];
__device__ int   g_cur[NN];
__device__ int   g_off[NN + 1];
__device__ int   g_csr[EE];
__device__ float g_dinv[NN];
__device__ int   g_is64;

// ---------------- edge dtype detection ----------------
// int64 edges (values in [0,2^31)): every odd 32-bit word is 0.
// int32 edges: odd words are random node ids — P(all 64 zero) ~ 0.
__global__ void k_detect(const unsigned* __restrict__ w) {
    if (threadIdx.x == 0) {
        int all0 = 1;
        for (int i = 1; i < 128; i += 2) all0 &= (w[i] == 0u);
        g_is64 = all0;
    }
}

__device__ __forceinline__ int edge_at(const void* ei, long long idx) {
    return g_is64 ? (int)((const long long*)ei)[idx]
                  : ((const int*)ei)[idx];
}

// ---------------- CSR build ----------------
__global__ void k_init(int n) {
    int i = blockIdx.x * blockDim.x + threadIdx.x;
    if (i < n) { g_cnt[i] = 0; g_cur[i] = 0; }
}

__global__ void k_count(const void* __restrict__ ei, int e, int n) {
    int i = blockIdx.x * blockDim.x + threadIdx.x;
    if (i < e) {
        int t = edge_at(ei, (long long)e + i);   // col = targets
        if ((unsigned)t < (unsigned)n) atomicAdd(&g_cnt[t], 1);
    }
}

// single-block exclusive scan of g_cnt -> g_off (chunked, 1024 threads)
__global__ void k_scan(int n) {
    __shared__ int wsum[32];
    __shared__ int s_total;
    int tid = threadIdx.x, lane = tid & 31, wid = tid >> 5;
    int carry = 0;
    for (int base = 0; base < n; base += 1024) {
        int i = base + tid;
        int v = (i < n) ? g_cnt[i] : 0;
        int incl = v;
#pragma unroll
        for (int d = 1; d < 32; d <<= 1) {
            int y = __shfl_up_sync(0xffffffffu, incl, d);
            if (lane >= d) incl += y;
        }
        if (lane == 31) wsum[wid] = incl;
        __syncthreads();
        if (wid == 0) {
            int s = wsum[lane];
#pragma unroll
            for (int d = 1; d < 32; d <<= 1) {
                int y = __shfl_up_sync(0xffffffffu, s, d);
                if (lane >= d) s += y;
            }
            wsum[lane] = s;
            if (lane == 31) s_total = s;
        }
        __syncthreads();
        int wprev = wid ? wsum[wid - 1] : 0;
        if (i < n) g_off[i] = carry + wprev + incl - v;
        carry += s_total;
        __syncthreads();
    }
    if (tid == 0) g_off[n] = carry;
}

__global__ void k_dinv(int n) {
    int i = blockIdx.x * blockDim.x + threadIdx.x;
    if (i < n) g_dinv[i] = rsqrtf((float)(g_cnt[i] + 1));  // +1 = self-loop
}

__global__ void k_fill(const void* __restrict__ ei, int e, int n) {
    int i = blockIdx.x * blockDim.x + threadIdx.x;
    if (i < e) {
        int t = edge_at(ei, (long long)e + i);   // target
        int s = edge_at(ei, i);                  // source
        if ((unsigned)t < (unsigned)n && (unsigned)s < (unsigned)n) {
            int p = atomicAdd(&g_cur[t], 1);
            g_csr[g_off[t] + p] = s;
        }
    }
}

// ---------------- GEMM1: h1w = x @ W1  [N,128]x[128,128] ----------------
// 32 rows/block, 256 threads, 4x4 microtile, k-tile = 32
__global__ void k_gemm1(const float* __restrict__ x,
                        const float* __restrict__ W1, int n) {
    __shared__ __align__(16) float Xs[32 * 36];   // [k][m], pad 36
    __shared__ __align__(16) float Ws[32 * 128];  // [k][c]
    int row0 = blockIdx.x * 32;
    int tid = threadIdx.x;
    int rm = (tid >> 5) * 4;   // row within tile (0..28)
    int cn = (tid & 31) * 4;   // col (0..124)
    float acc[4][4] = {};

    for (int kk = 0; kk < DD; kk += 32) {
        // X tile (transposed into smem)
#pragma unroll
        for (int j = 0; j < 4; j++) {
            int i = tid + j * 256;
            int m = i >> 5, k = i & 31;
            int r = row0 + m;
            Xs[k * 36 + m] = (r < n) ? x[(size_t)r * DD + kk + k] : 0.f;
        }
        // W tile (float4 copy)
#pragma unroll
        for (int j = 0; j < 4; j++) {
            int i = tid + j * 256;          // 1024 float4 slots
            int k = i >> 5, c4 = i & 31;
            ((float4*)Ws)[k * 32 + c4] =
                ((const float4*)W1)[(size_t)(kk + k) * 32 + c4];
        }
        __syncthreads();
#pragma unroll
        for (int k = 0; k < 32; k++) {
            float4 xa = *(const float4*)&Xs[k * 36 + rm];
            float4 wb = *(const float4*)&Ws[k * 128 + cn];
            acc[0][0] += xa.x * wb.x; acc[0][1] += xa.x * wb.y;
            acc[0][2] += xa.x * wb.z; acc[0][3] += xa.x * wb.w;
            acc[1][0] += xa.y * wb.x; acc[1][1] += xa.y * wb.y;
            acc[1][2] += xa.y * wb.z; acc[1][3] += xa.y * wb.w;
            acc[2][0] += xa.z * wb.x; acc[2][1] += xa.z * wb.y;
            acc[2][2] += xa.z * wb.z; acc[2][3] += xa.z * wb.w;
            acc[3][0] += xa.w * wb.x; acc[3][1] += xa.w * wb.y;
            acc[3][2] += xa.w * wb.z; acc[3][3] += xa.w * wb.w;
        }
        __syncthreads();
    }
#pragma unroll
    for (int r = 0; r < 4; r++) {
        int gr = row0 + rm + r;
        if (gr < n) {
            float4 o = make_float4(acc[r][0], acc[r][1], acc[r][2], acc[r][3]);
            *(float4*)&g_h1w[(size_t)gr * DD + cn] = o;
        }
    }
}

// ---------------- Aggregate layer 1 (warp per node, gather-side) ----------------
__global__ void k_agg1(const float* __restrict__ b1, int n) {
    int gw = (blockIdx.x * blockDim.x + threadIdx.x) >> 5;
    int lane = threadIdx.x & 31;
    if (gw >= n) return;
    float dn = g_dinv[gw];
    const float4* h = (const float4*)g_h1w;
    float4 a = h[(size_t)gw * 32 + lane];
    float s = dn * dn;
    a.x *= s; a.y *= s; a.z *= s; a.w *= s;
    int e0 = g_off[gw], e1 = g_off[gw + 1];
    for (int e = e0; e < e1; e++) {
        int src = g_csr[e];
        float w = g_dinv[src] * dn;
        float4 v = h[(size_t)src * 32 + lane];
        a.x += v.x * w; a.y += v.y * w; a.z += v.z * w; a.w += v.w * w;
    }
    float4 b = ((const float4*)b1)[lane];
    a.x = fmaxf(a.x + b.x, 0.f);
    a.y = fmaxf(a.y + b.y, 0.f);
    a.z = fmaxf(a.z + b.z, 0.f);
    a.w = fmaxf(a.w + b.w, 0.f);
    ((float4*)g_agg1)[(size_t)gw * 32 + lane] = a;
}

// ---------------- h2w = agg1 @ W2  (warp per node, D_OUT=2) ----------------
__global__ void k_h2w(const float* __restrict__ W2, int n) {
    int gw = (blockIdx.x * blockDim.x + threadIdx.x) >> 5;
    int lane = threadIdx.x & 31;
    if (gw >= n) return;
    float4 a = ((const float4*)g_agg1)[(size_t)gw * 32 + lane];
    const float2* w = (const float2*)W2;
    float2 w0 = w[lane * 4 + 0], w1 = w[lane * 4 + 1];
    float2 w2 = w[lane * 4 + 2], w3 = w[lane * 4 + 3];
    float o0 = a.x * w0.x + a.y * w1.x + a.z * w2.x + a.w * w3.x;
    float o1 = a.x * w0.y + a.y * w1.y + a.z * w2.y + a.w * w3.y;
#pragma unroll
    for (int d = 16; d; d >>= 1) {
        o0 += __shfl_xor_sync(0xffffffffu, o0, d);
        o1 += __shfl_xor_sync(0xffffffffu, o1, d);
    }
    if (lane == 0) g_h2w[gw] = make_float2(o0, o1);
}

// ---------------- Aggregate layer 2 (thread per node) ----------------
__global__ void k_agg2(const float* __restrict__ b2, float* __restrict__ out, int n) {
    int i = blockIdx.x * blockDim.x + threadIdx.x;
    if (i >= n) return;
    float dn = g_dinv[i];
    float2 hv = g_h2w[i];
    float o0 = hv.x * dn * dn + b2[0];
    float o1 = hv.y * dn * dn + b2[1];
    int e0 = g_off[i], e1 = g_off[i + 1];
    for (int e = e0; e < e1; e++) {
        int src = g_csr[e];
        float w = g_dinv[src] * dn;
        float2 v = g_h2w[src];
        o0 += v.x * w;
        o1 += v.y * w;
    }
    ((float2*)out)[i] = make_float2(o0, o1);
}

// ---------------- launch ----------------
extern "C" void kernel_launch(void* const* d_in, const int* in_sizes, int n_in,
                              void* d_out, int out_size) {
    const float* x  = (const float*)d_in[0];
    const void*  ei = d_in[1];
    const float* W1 = (const float*)d_in[2];
    const float* b1 = (const float*)d_in[3];
    const float* W2 = (const float*)d_in[4];
    const float* b2 = (const float*)d_in[5];
    float* out = (float*)d_out;

    const int n = in_sizes[0] / DD;       // 100000
    const int e = in_sizes[1] / 2;        // 600000

    k_detect<<<1, 32>>>((const unsigned*)ei);
    k_init<<<(n + 255) / 256, 256>>>(n);
    k_count<<<(e + 255) / 256, 256>>>(ei, e, n);
    k_scan<<<1, 1024>>>(n);
    k_dinv<<<(n + 255) / 256, 256>>>(n);
    k_fill<<<(e + 255) / 256, 256>>>(ei, e, n);
    k_gemm1<<<(n + 31) / 32, 256>>>(x, W1, n);
    k_agg1<<<(n + 7) / 8, 256>>>(b1, n);
    k_h2w<<<(n + 7) / 8, 256>>>(W2, n);
    k_agg2<<<(n + 255) / 256, 256>>>(b2, out, n);
}

// round 4
// speedup vs baseline: 1.3220x; 1.3220x over previous
#include <cuda_runtime.h>

#define NN 100000
#define EE 600000
#define DD 128
#define SCAN_B 1024
#define NBLK ((NN + SCAN_B - 1) / SCAN_B)   // 98

// ---- device scratch (allocation-free rule: __device__ globals) ----
__device__ __align__(16) float g_h1w[(size_t)NN * DD];   // x @ W1
__device__ __align__(16) float g_agg1[(size_t)NN * DD];  // relu(aggregate + b1)
__device__ __align__(16) float2 g_h2w[NN];               // agg1 @ W2
__device__ int   g_cnt[NN];
__device__ int   g_cur[NN];
__device__ int   g_off[NN + 1];
__device__ int   g_bsum[NBLK + 1];
__device__ int   g_csr[EE];
__device__ float g_dinv[NN];
__device__ int   g_is64;

// ---------------- edge dtype detection ----------------
// int64 edges (values in [0,2^31)): every odd 32-bit word is 0.
// int32 edges: odd words are random node ids — P(all 64 zero) ~ 0.
__global__ void k_detect(const unsigned* __restrict__ w) {
    if (threadIdx.x == 0) {
        int all0 = 1;
        for (int i = 1; i < 128; i += 2) all0 &= (w[i] == 0u);
        g_is64 = all0;
    }
}

__device__ __forceinline__ int edge_at(const void* ei, long long idx) {
    return g_is64 ? (int)((const long long*)ei)[idx]
                  : ((const int*)ei)[idx];
}

// ---------------- CSR build ----------------
__global__ void k_init(int n) {
    int i = blockIdx.x * blockDim.x + threadIdx.x;
    if (i < n) { g_cnt[i] = 0; g_cur[i] = 0; }
}

__global__ void k_count(const void* __restrict__ ei, int e, int n) {
    int i = blockIdx.x * blockDim.x + threadIdx.x;
    if (i < e) {
        int t = edge_at(ei, (long long)e + i);   // col = targets
        if ((unsigned)t < (unsigned)n) atomicAdd(&g_cnt[t], 1);
    }
}

// stage 1: per-block exclusive scan of g_cnt into g_off; block total -> g_bsum
__global__ void k_scan1(int n) {
    __shared__ int wsum[32];
    int tid = threadIdx.x, lane = tid & 31, wid = tid >> 5;
    int i = blockIdx.x * SCAN_B + tid;
    int v = (i < n) ? g_cnt[i] : 0;
    int incl = v;
#pragma unroll
    for (int d = 1; d < 32; d <<= 1) {
        int y = __shfl_up_sync(0xffffffffu, incl, d);
        if (lane >= d) incl += y;
    }
    if (lane == 31) wsum[wid] = incl;
    __syncthreads();
    if (wid == 0) {
        int s = wsum[lane];
#pragma unroll
        for (int d = 1; d < 32; d <<= 1) {
            int y = __shfl_up_sync(0xffffffffu, s, d);
            if (lane >= d) s += y;
        }
        wsum[lane] = s;
    }
    __syncthreads();
    int wprev = wid ? wsum[wid - 1] : 0;
    if (i < n) g_off[i] = wprev + incl - v;       // in-block exclusive
    if (tid == SCAN_B - 1) g_bsum[blockIdx.x] = wprev + incl;  // block total
}

// stage 2: exclusive scan of nb (<=98) block sums (1 block, 128 threads)
__global__ void k_scan2(int nb) {
    __shared__ int wsum[4];
    int tid = threadIdx.x, lane = tid & 31, wid = tid >> 5;
    int v = (tid < nb) ? g_bsum[tid] : 0;
    int incl = v;
#pragma unroll
    for (int d = 1; d < 32; d <<= 1) {
        int y = __shfl_up_sync(0xffffffffu, incl, d);
        if (lane >= d) incl += y;
    }
    if (lane == 31) wsum[wid] = incl;
    __syncthreads();
    int wprev = 0;
    for (int j = 0; j < wid; j++) wprev += wsum[j];
    int excl = wprev + incl - v;
    if (tid < nb) g_bsum[tid] = excl;                       // exclusive
    if (tid == nb - 1) g_bsum[nb] = wprev + incl;           // grand total
}

// stage 3: propagate block offsets; fuse dinv; write g_off[n]
__global__ void k_scan3(int n, int nb) {
    int i = blockIdx.x * SCAN_B + threadIdx.x;
    if (i < n) {
        g_off[i] += g_bsum[blockIdx.x];
        g_dinv[i] = rsqrtf((float)(g_cnt[i] + 1));  // +1 = self-loop
    }
    if (i == 0) g_off[n] = g_bsum[nb];
}

__global__ void k_fill(const void* __restrict__ ei, int e, int n) {
    int i = blockIdx.x * blockDim.x + threadIdx.x;
    if (i < e) {
        int t = edge_at(ei, (long long)e + i);   // target
        int s = edge_at(ei, i);                  // source
        if ((unsigned)t < (unsigned)n && (unsigned)s < (unsigned)n) {
            int p = atomicAdd(&g_cur[t], 1);
            g_csr[g_off[t] + p] = s;
        }
    }
}

// ---------------- GEMM1: h1w = x @ W1  [N,128]x[128,128] ----------------
// 32 rows/block, 256 threads, 4x4 microtile, k-tile = 32
__global__ void k_gemm1(const float* __restrict__ x,
                        const float* __restrict__ W1, int n) {
    __shared__ __align__(16) float Xs[32 * 36];   // [k][m], pad 36
    __shared__ __align__(16) float Ws[32 * 128];  // [k][c]
    int row0 = blockIdx.x * 32;
    int tid = threadIdx.x;
    int rm = (tid >> 5) * 4;   // row within tile (0..28)
    int cn = (tid & 31) * 4;   // col (0..124)
    float acc[4][4] = {};

    for (int kk = 0; kk < DD; kk += 32) {
        // X tile (transposed into smem)
#pragma unroll
        for (int j = 0; j < 4; j++) {
            int i = tid + j * 256;
            int m = i >> 5, k = i & 31;
            int r = row0 + m;
            Xs[k * 36 + m] = (r < n) ? x[(size_t)r * DD + kk + k] : 0.f;
        }
        // W tile (float4 copy)
#pragma unroll
        for (int j = 0; j < 4; j++) {
            int i = tid + j * 256;          // 1024 float4 slots
            int k = i >> 5, c4 = i & 31;
            ((float4*)Ws)[k * 32 + c4] =
                ((const float4*)W1)[(size_t)(kk + k) * 32 + c4];
        }
        __syncthreads();
#pragma unroll
        for (int k = 0; k < 32; k++) {
            float4 xa = *(const float4*)&Xs[k * 36 + rm];
            float4 wb = *(const float4*)&Ws[k * 128 + cn];
            acc[0][0] += xa.x * wb.x; acc[0][1] += xa.x * wb.y;
            acc[0][2] += xa.x * wb.z; acc[0][3] += xa.x * wb.w;
            acc[1][0] += xa.y * wb.x; acc[1][1] += xa.y * wb.y;
            acc[1][2] += xa.y * wb.z; acc[1][3] += xa.y * wb.w;
            acc[2][0] += xa.z * wb.x; acc[2][1] += xa.z * wb.y;
            acc[2][2] += xa.z * wb.z; acc[2][3] += xa.z * wb.w;
            acc[3][0] += xa.w * wb.x; acc[3][1] += xa.w * wb.y;
            acc[3][2] += xa.w * wb.z; acc[3][3] += xa.w * wb.w;
        }
        __syncthreads();
    }
#pragma unroll
    for (int r = 0; r < 4; r++) {
        int gr = row0 + rm + r;
        if (gr < n) {
            float4 o = make_float4(acc[r][0], acc[r][1], acc[r][2], acc[r][3]);
            *(float4*)&g_h1w[(size_t)gr * DD + cn] = o;
        }
    }
}

// ---------------- Aggregate layer 1 (warp per node, gather-side) ----------------
__global__ void k_agg1(const float* __restrict__ b1, int n) {
    int gw = (blockIdx.x * blockDim.x + threadIdx.x) >> 5;
    int lane = threadIdx.x & 31;
    if (gw >= n) return;
    float dn = g_dinv[gw];
    const float4* h = (const float4*)g_h1w;
    float4 a = h[(size_t)gw * 32 + lane];
    float s = dn * dn;
    a.x *= s; a.y *= s; a.z *= s; a.w *= s;
    int e0 = g_off[gw], e1 = g_off[gw + 1];
    for (int e = e0; e < e1; e++) {
        int src = g_csr[e];
        float w = g_dinv[src] * dn;
        float4 v = h[(size_t)src * 32 + lane];
        a.x += v.x * w; a.y += v.y * w; a.z += v.z * w; a.w += v.w * w;
    }
    float4 b = ((const float4*)b1)[lane];
    a.x = fmaxf(a.x + b.x, 0.f);
    a.y = fmaxf(a.y + b.y, 0.f);
    a.z = fmaxf(a.z + b.z, 0.f);
    a.w = fmaxf(a.w + b.w, 0.f);
    ((float4*)g_agg1)[(size_t)gw * 32 + lane] = a;
}

// ---------------- h2w = agg1 @ W2  (warp per node, D_OUT=2) ----------------
__global__ void k_h2w(const float* __restrict__ W2, int n) {
    int gw = (blockIdx.x * blockDim.x + threadIdx.x) >> 5;
    int lane = threadIdx.x & 31;
    if (gw >= n) return;
    float4 a = ((const float4*)g_agg1)[(size_t)gw * 32 + lane];
    const float2* w = (const float2*)W2;
    float2 w0 = w[lane * 4 + 0], w1 = w[lane * 4 + 1];
    float2 w2 = w[lane * 4 + 2], w3 = w[lane * 4 + 3];
    float o0 = a.x * w0.x + a.y * w1.x + a.z * w2.x + a.w * w3.x;
    float o1 = a.x * w0.y + a.y * w1.y + a.z * w2.y + a.w * w3.y;
#pragma unroll
    for (int d = 16; d; d >>= 1) {
        o0 += __shfl_xor_sync(0xffffffffu, o0, d);
        o1 += __shfl_xor_sync(0xffffffffu, o1, d);
    }
    if (lane == 0) g_h2w[gw] = make_float2(o0, o1);
}

// ---------------- Aggregate layer 2 (thread per node) ----------------
__global__ void k_agg2(const float* __restrict__ b2, float* __restrict__ out, int n) {
    int i = blockIdx.x * blockDim.x + threadIdx.x;
    if (i >= n) return;
    float dn = g_dinv[i];
    float2 hv = g_h2w[i];
    float o0 = hv.x * dn * dn + b2[0];
    float o1 = hv.y * dn * dn + b2[1];
    int e0 = g_off[i], e1 = g_off[i + 1];
    for (int e = e0; e < e1; e++) {
        int src = g_csr[e];
        float w = g_dinv[src] * dn;
        float2 v = g_h2w[src];
        o0 += v.x * w;
        o1 += v.y * w;
    }
    ((float2*)out)[i] = make_float2(o0, o1);
}

// ---------------- launch ----------------
extern "C" void kernel_launch(void* const* d_in, const int* in_sizes, int n_in,
                              void* d_out, int out_size) {
    const float* x  = (const float*)d_in[0];
    const void*  ei = d_in[1];
    const float* W1 = (const float*)d_in[2];
    const float* b1 = (const float*)d_in[3];
    const float* W2 = (const float*)d_in[4];
    const float* b2 = (const float*)d_in[5];
    float* out = (float*)d_out;

    const int n = in_sizes[0] / DD;       // 100000
    const int e = in_sizes[1] / 2;        // 600000
    const int nb = (n + SCAN_B - 1) / SCAN_B;

    k_detect<<<1, 32>>>((const unsigned*)ei);
    k_init<<<(n + 255) / 256, 256>>>(n);
    k_count<<<(e + 255) / 256, 256>>>(ei, e, n);
    k_scan1<<<nb, SCAN_B>>>(n);
    k_scan2<<<1, 128>>>(nb);
    k_scan3<<<nb, SCAN_B>>>(n, nb);
    k_fill<<<(e + 255) / 256, 256>>>(ei, e, n);
    k_gemm1<<<(n + 31) / 32, 256>>>(x, W1, n);
    k_agg1<<<(n + 7) / 8, 256>>>(b1, n);
    k_h2w<<<(n + 7) / 8, 256>>>(W2, n);
    k_agg2<<<(n + 255) / 256, 256>>>(b2, out, n);
}

// round 5
// speedup vs baseline: 1.5882x; 1.2014x over previous
#include <cuda_runtime.h>
#include <cstdint>

#define NN 100000
#define EE 600000
#define DD 128
#define SCAN_B 1024
#define NBLK ((NN + SCAN_B - 1) / SCAN_B)   // 98

// ---- device scratch (allocation-free rule: __device__ globals) ----
__device__ __align__(16) float g_h1w[(size_t)NN * DD];   // x @ W1
__device__ __align__(16) float2 g_h2w[NN];               // relu(agg1+b1) @ W2
__device__ int   g_cnt[NN];
__device__ int   g_cur[NN];
__device__ int   g_off[NN + 1];
__device__ int   g_bsum[NBLK + 1];
__device__ int   g_csr[EE];
__device__ float g_dinv[NN];
__device__ int   g_is64;

// ---------------- edge dtype detection ----------------
__global__ void k_detect(const unsigned* __restrict__ w) {
    if (threadIdx.x == 0) {
        int all0 = 1;
        for (int i = 1; i < 128; i += 2) all0 &= (w[i] == 0u);
        g_is64 = all0;
    }
}

__device__ __forceinline__ int edge_at(const void* ei, long long idx) {
    return g_is64 ? (int)((const long long*)ei)[idx]
                  : ((const int*)ei)[idx];
}

// ---------------- CSR build ----------------
__global__ void k_init(int n) {
    int i = blockIdx.x * blockDim.x + threadIdx.x;
    if (i < n) { g_cnt[i] = 0; g_cur[i] = 0; }
}

__global__ void k_count(const void* __restrict__ ei, int e, int n) {
    int i = blockIdx.x * blockDim.x + threadIdx.x;
    if (i < e) {
        int t = edge_at(ei, (long long)e + i);
        if ((unsigned)t < (unsigned)n) atomicAdd(&g_cnt[t], 1);
    }
}

__global__ void k_scan1(int n) {
    __shared__ int wsum[32];
    int tid = threadIdx.x, lane = tid & 31, wid = tid >> 5;
    int i = blockIdx.x * SCAN_B + tid;
    int v = (i < n) ? g_cnt[i] : 0;
    int incl = v;
#pragma unroll
    for (int d = 1; d < 32; d <<= 1) {
        int y = __shfl_up_sync(0xffffffffu, incl, d);
        if (lane >= d) incl += y;
    }
    if (lane == 31) wsum[wid] = incl;
    __syncthreads();
    if (wid == 0) {
        int s = wsum[lane];
#pragma unroll
        for (int d = 1; d < 32; d <<= 1) {
            int y = __shfl_up_sync(0xffffffffu, s, d);
            if (lane >= d) s += y;
        }
        wsum[lane] = s;
    }
    __syncthreads();
    int wprev = wid ? wsum[wid - 1] : 0;
    if (i < n) g_off[i] = wprev + incl - v;
    if (tid == SCAN_B - 1) g_bsum[blockIdx.x] = wprev + incl;
}

__global__ void k_scan2(int nb) {
    __shared__ int wsum[4];
    int tid = threadIdx.x, lane = tid & 31, wid = tid >> 5;
    int v = (tid < nb) ? g_bsum[tid] : 0;
    int incl = v;
#pragma unroll
    for (int d = 1; d < 32; d <<= 1) {
        int y = __shfl_up_sync(0xffffffffu, incl, d);
        if (lane >= d) incl += y;
    }
    if (lane == 31) wsum[wid] = incl;
    __syncthreads();
    int wprev = 0;
    for (int j = 0; j < wid; j++) wprev += wsum[j];
    int excl = wprev + incl - v;
    if (tid < nb) g_bsum[tid] = excl;
    if (tid == nb - 1) g_bsum[nb] = wprev + incl;
}

__global__ void k_scan3(int n, int nb) {
    int i = blockIdx.x * SCAN_B + threadIdx.x;
    if (i < n) {
        g_off[i] += g_bsum[blockIdx.x];
        g_dinv[i] = rsqrtf((float)(g_cnt[i] + 1));
    }
    if (i == 0) g_off[n] = g_bsum[nb];
}

__global__ void k_fill(const void* __restrict__ ei, int e, int n) {
    int i = blockIdx.x * blockDim.x + threadIdx.x;
    if (i < e) {
        int t = edge_at(ei, (long long)e + i);
        int s = edge_at(ei, i);
        if ((unsigned)t < (unsigned)n && (unsigned)s < (unsigned)n) {
            int p = atomicAdd(&g_cur[t], 1);
            g_csr[g_off[t] + p] = s;
        }
    }
}

// ---------------- GEMM1 via tf32 tensor cores (3xtf32 compensated) ----------------
__device__ __forceinline__ uint32_t f2tf(float f) {
    uint32_t u;
    asm("cvt.rna.tf32.f32 %0, %1;" : "=r"(u) : "f"(f));
    return u;
}

__device__ __forceinline__ void mma8(float* c, const uint32_t* a, const uint32_t* b) {
    asm volatile(
        "mma.sync.aligned.m16n8k8.row.col.f32.tf32.tf32.f32 "
        "{%0,%1,%2,%3},{%4,%5,%6,%7},{%8,%9},{%0,%1,%2,%3};"
        : "+f"(c[0]), "+f"(c[1]), "+f"(c[2]), "+f"(c[3])
        : "r"(a[0]), "r"(a[1]), "r"(a[2]), "r"(a[3]), "r"(b[0]), "r"(b[1]));
}

#define SX 136   // smem row stride (conflict-free: bank = 8*tig + gid)

__global__ void __launch_bounds__(256, 2)
k_gemm1_tc(const float* __restrict__ x, const float* __restrict__ W1, int n) {
    __shared__ uint32_t Xh[16 * SX], Xl[16 * SX];   // [k][row]
    __shared__ uint32_t Wh[16 * SX], Wl[16 * SX];   // [k][col]
    int tid = threadIdx.x;
    int wid = tid >> 5, lane = tid & 31;
    int gid = lane >> 2, tig = lane & 3;
    int warpM = wid & 3;          // 4 warps over M (32 rows each)
    int warpN = wid >> 2;         // 2 warps over N (64 cols each)
    int row0 = blockIdx.x * 128;

    float acc[2][8][4];
#pragma unroll
    for (int mt = 0; mt < 2; mt++)
#pragma unroll
        for (int nt = 0; nt < 8; nt++)
#pragma unroll
            for (int j = 0; j < 4; j++) acc[mt][nt][j] = 0.f;

    for (int kk = 0; kk < DD; kk += 16) {
        // load X chunk [128 rows x 16 k], split hi/lo, transpose to [k][row]
#pragma unroll
        for (int j = 0; j < 2; j++) {
            int idx = tid + j * 256;        // 512 float4
            int r = idx >> 2, kq = idx & 3;
            float4 v = make_float4(0.f, 0.f, 0.f, 0.f);
            if (row0 + r < n)
                v = *(const float4*)(x + (size_t)(row0 + r) * DD + kk + kq * 4);
            float f[4] = {v.x, v.y, v.z, v.w};
#pragma unroll
            for (int i = 0; i < 4; i++) {
                uint32_t h = f2tf(f[i]);
                Xh[(kq * 4 + i) * SX + r] = h;
                Xl[(kq * 4 + i) * SX + r] = f2tf(f[i] - __uint_as_float(h));
            }
        }
        // load W chunk [16 k x 128 n], split hi/lo, layout [k][n]
#pragma unroll
        for (int j = 0; j < 2; j++) {
            int idx = tid + j * 256;        // 512 float4
            int k = idx >> 5, n4 = idx & 31;
            float4 v = ((const float4*)W1)[(size_t)(kk + k) * 32 + n4];
            float f[4] = {v.x, v.y, v.z, v.w};
#pragma unroll
            for (int i = 0; i < 4; i++) {
                uint32_t h = f2tf(f[i]);
                Wh[k * SX + n4 * 4 + i] = h;
                Wl[k * SX + n4 * 4 + i] = f2tf(f[i] - __uint_as_float(h));
            }
        }
        __syncthreads();

#pragma unroll
        for (int kb = 0; kb < 16; kb += 8) {
            uint32_t ah[2][4], al[2][4];
#pragma unroll
            for (int mt = 0; mt < 2; mt++) {
                int r = warpM * 32 + mt * 16 + gid;
                int kr0 = (kb + tig) * SX, kr4 = (kb + tig + 4) * SX;
                ah[mt][0] = Xh[kr0 + r];     al[mt][0] = Xl[kr0 + r];
                ah[mt][1] = Xh[kr0 + r + 8]; al[mt][1] = Xl[kr0 + r + 8];
                ah[mt][2] = Xh[kr4 + r];     al[mt][2] = Xl[kr4 + r];
                ah[mt][3] = Xh[kr4 + r + 8]; al[mt][3] = Xl[kr4 + r + 8];
            }
#pragma unroll
            for (int nt = 0; nt < 8; nt++) {
                int c = warpN * 64 + nt * 8 + gid;
                uint32_t bh[2], bl[2];
                bh[0] = Wh[(kb + tig) * SX + c];     bh[1] = Wh[(kb + tig + 4) * SX + c];
                bl[0] = Wl[(kb + tig) * SX + c];     bl[1] = Wl[(kb + tig + 4) * SX + c];
#pragma unroll
                for (int mt = 0; mt < 2; mt++) {
                    mma8(acc[mt][nt], ah[mt], bh);   // Ah*Bh
                    mma8(acc[mt][nt], al[mt], bh);   // Al*Bh
                    mma8(acc[mt][nt], ah[mt], bl);   // Ah*Bl
                }
            }
        }
        __syncthreads();
    }

    // epilogue
#pragma unroll
    for (int mt = 0; mt < 2; mt++) {
#pragma unroll
        for (int nt = 0; nt < 8; nt++) {
            int row = row0 + warpM * 32 + mt * 16 + gid;
            int col = warpN * 64 + nt * 8 + 2 * tig;
            if (row < n)
                *(float2*)&g_h1w[(size_t)row * DD + col] =
                    make_float2(acc[mt][nt][0], acc[mt][nt][1]);
            if (row + 8 < n)
                *(float2*)&g_h1w[(size_t)(row + 8) * DD + col] =
                    make_float2(acc[mt][nt][2], acc[mt][nt][3]);
        }
    }
}

// ------- Aggregate layer 1 + bias + relu + W2 projection (fused, warp/node) -------
__global__ void k_agg1(const float* __restrict__ b1,
                       const float* __restrict__ W2, int n) {
    int gw = (blockIdx.x * blockDim.x + threadIdx.x) >> 5;
    int lane = threadIdx.x & 31;
    if (gw >= n) return;
    float dn = g_dinv[gw];
    const float4* h = (const float4*)g_h1w;
    float4 a = h[(size_t)gw * 32 + lane];
    float s = dn * dn;
    a.x *= s; a.y *= s; a.z *= s; a.w *= s;
    int e0 = g_off[gw], e1 = g_off[gw + 1];
    for (int e = e0; e < e1; e++) {
        int src = g_csr[e];
        float w = g_dinv[src] * dn;
        float4 v = h[(size_t)src * 32 + lane];
        a.x += v.x * w; a.y += v.y * w; a.z += v.z * w; a.w += v.w * w;
    }
    float4 b = ((const float4*)b1)[lane];
    a.x = fmaxf(a.x + b.x, 0.f);
    a.y = fmaxf(a.y + b.y, 0.f);
    a.z = fmaxf(a.z + b.z, 0.f);
    a.w = fmaxf(a.w + b.w, 0.f);
    // fused W2 projection (D_OUT = 2)
    const float2* w2 = (const float2*)W2;
    float2 w0 = w2[lane * 4 + 0], w1 = w2[lane * 4 + 1];
    float2 w2v = w2[lane * 4 + 2], w3 = w2[lane * 4 + 3];
    float o0 = a.x * w0.x + a.y * w1.x + a.z * w2v.x + a.w * w3.x;
    float o1 = a.x * w0.y + a.y * w1.y + a.z * w2v.y + a.w * w3.y;
#pragma unroll
    for (int d = 16; d; d >>= 1) {
        o0 += __shfl_xor_sync(0xffffffffu, o0, d);
        o1 += __shfl_xor_sync(0xffffffffu, o1, d);
    }
    if (lane == 0) g_h2w[gw] = make_float2(o0, o1);
}

// ---------------- Aggregate layer 2 (thread per node) ----------------
__global__ void k_agg2(const float* __restrict__ b2, float* __restrict__ out, int n) {
    int i = blockIdx.x * blockDim.x + threadIdx.x;
    if (i >= n) return;
    float dn = g_dinv[i];
    float2 hv = g_h2w[i];
    float o0 = hv.x * dn * dn + b2[0];
    float o1 = hv.y * dn * dn + b2[1];
    int e0 = g_off[i], e1 = g_off[i + 1];
    for (int e = e0; e < e1; e++) {
        int src = g_csr[e];
        float w = g_dinv[src] * dn;
        float2 v = g_h2w[src];
        o0 += v.x * w;
        o1 += v.y * w;
    }
    ((float2*)out)[i] = make_float2(o0, o1);
}

// ---------------- launch ----------------
extern "C" void kernel_launch(void* const* d_in, const int* in_sizes, int n_in,
                              void* d_out, int out_size) {
    const float* x  = (const float*)d_in[0];
    const void*  ei = d_in[1];
    const float* W1 = (const float*)d_in[2];
    const float* b1 = (const float*)d_in[3];
    const float* W2 = (const float*)d_in[4];
    const float* b2 = (const float*)d_in[5];
    float* out = (float*)d_out;

    const int n = in_sizes[0] / DD;       // 100000
    const int e = in_sizes[1] / 2;        // 600000
    const int nb = (n + SCAN_B - 1) / SCAN_B;

    k_detect<<<1, 32>>>((const unsigned*)ei);
    k_init<<<(n + 255) / 256, 256>>>(n);
    k_count<<<(e + 255) / 256, 256>>>(ei, e, n);
    k_scan1<<<nb, SCAN_B>>>(n);
    k_scan2<<<1, 128>>>(nb);
    k_scan3<<<nb, SCAN_B>>>(n, nb);
    k_fill<<<(e + 255) / 256, 256>>>(ei, e, n);
    k_gemm1_tc<<<(n + 127) / 128, 256>>>(x, W1, n);
    k_agg1<<<(n + 7) / 8, 256>>>(b1, W2, n);
    k_agg2<<<(n + 255) / 256, 256>>>(b2, out, n);
}

// round 6
// speedup vs baseline: 1.6100x; 1.0137x over previous
#include <cuda_runtime.h>
#include <cstdint>

#define NN 100000
#define EE 600000
#define DD 128
#define SCAN_B 1024
#define NBLK ((NN + SCAN_B - 1) / SCAN_B)   // 98

// ---- device scratch (allocation-free rule: __device__ globals) ----
__device__ __align__(16) float g_h1w[(size_t)NN * DD];   // x @ W1
__device__ __align__(16) float2 g_h2w[NN];               // relu(agg1+b1) @ W2
__device__ __align__(16) uint32_t g_wh[DD * DD];         // tf32 hi split of W1
__device__ __align__(16) uint32_t g_wl[DD * DD];         // tf32 lo split of W1
__device__ int   g_cnt[NN];
__device__ int   g_cur[NN];
__device__ int   g_off[NN + 1];
__device__ int   g_bsum[NBLK + 1];
__device__ int   g_csr[EE];
__device__ float g_dinv[NN];
__device__ int   g_is64;

// ---------------- init + edge dtype detection (fused) ----------------
// int64 edges (values in [0,2^31)): every odd 32-bit word is 0.
__global__ void k_init(int n, const unsigned* __restrict__ w) {
    int i = blockIdx.x * blockDim.x + threadIdx.x;
    if (i < n) { g_cnt[i] = 0; g_cur[i] = 0; }
    if (i == 0) {
        int all0 = 1;
        for (int j = 1; j < 128; j += 2) all0 &= (w[j] == 0u);
        g_is64 = all0;
    }
}

__device__ __forceinline__ int edge_at(const void* ei, long long idx) {
    return g_is64 ? (int)((const long long*)ei)[idx]
                  : ((const int*)ei)[idx];
}

__global__ void k_count(const void* __restrict__ ei, int e, int n) {
    int i = blockIdx.x * blockDim.x + threadIdx.x;
    if (i < e) {
        int t = edge_at(ei, (long long)e + i);
        if ((unsigned)t < (unsigned)n) atomicAdd(&g_cnt[t], 1);
    }
}

__global__ void k_scan1(int n) {
    __shared__ int wsum[32];
    int tid = threadIdx.x, lane = tid & 31, wid = tid >> 5;
    int i = blockIdx.x * SCAN_B + tid;
    int v = (i < n) ? g_cnt[i] : 0;
    int incl = v;
#pragma unroll
    for (int d = 1; d < 32; d <<= 1) {
        int y = __shfl_up_sync(0xffffffffu, incl, d);
        if (lane >= d) incl += y;
    }
    if (lane == 31) wsum[wid] = incl;
    __syncthreads();
    if (wid == 0) {
        int s = wsum[lane];
#pragma unroll
        for (int d = 1; d < 32; d <<= 1) {
            int y = __shfl_up_sync(0xffffffffu, s, d);
            if (lane >= d) s += y;
        }
        wsum[lane] = s;
    }
    __syncthreads();
    int wprev = wid ? wsum[wid - 1] : 0;
    if (i < n) g_off[i] = wprev + incl - v;
    if (tid == SCAN_B - 1) g_bsum[blockIdx.x] = wprev + incl;
}

__global__ void k_scan2(int nb) {
    __shared__ int wsum[4];
    int tid = threadIdx.x, lane = tid & 31, wid = tid >> 5;
    int v = (tid < nb) ? g_bsum[tid] : 0;
    int incl = v;
#pragma unroll
    for (int d = 1; d < 32; d <<= 1) {
        int y = __shfl_up_sync(0xffffffffu, incl, d);
        if (lane >= d) incl += y;
    }
    if (lane == 31) wsum[wid] = incl;
    __syncthreads();
    int wprev = 0;
    for (int j = 0; j < wid; j++) wprev += wsum[j];
    int excl = wprev + incl - v;
    if (tid < nb) g_bsum[tid] = excl;
    if (tid == nb - 1) g_bsum[nb] = wprev + incl;
}

__global__ void k_scan3(int n, int nb) {
    int i = blockIdx.x * SCAN_B + threadIdx.x;
    if (i < n) {
        g_off[i] += g_bsum[blockIdx.x];
        g_dinv[i] = rsqrtf((float)(g_cnt[i] + 1));
    }
    if (i == 0) g_off[n] = g_bsum[nb];
}

__global__ void k_fill(const void* __restrict__ ei, int e, int n) {
    int i = blockIdx.x * blockDim.x + threadIdx.x;
    if (i < e) {
        int t = edge_at(ei, (long long)e + i);
        int s = edge_at(ei, i);
        if ((unsigned)t < (unsigned)n && (unsigned)s < (unsigned)n) {
            int p = atomicAdd(&g_cur[t], 1);
            g_csr[g_off[t] + p] = s;
        }
    }
}

// ---------------- tf32 helpers ----------------
__device__ __forceinline__ uint32_t f2tf(float f) {
    uint32_t u;
    asm("cvt.rna.tf32.f32 %0, %1;" : "=r"(u) : "f"(f));
    return u;
}

__device__ __forceinline__ void mma8(float* c, const uint32_t* a, const uint32_t* b) {
    asm volatile(
        "mma.sync.aligned.m16n8k8.row.col.f32.tf32.tf32.f32 "
        "{%0,%1,%2,%3},{%4,%5,%6,%7},{%8,%9},{%0,%1,%2,%3};"
        : "+f"(c[0]), "+f"(c[1]), "+f"(c[2]), "+f"(c[3])
        : "r"(a[0]), "r"(a[1]), "r"(a[2]), "r"(a[3]), "r"(b[0]), "r"(b[1]));
}

// one-time tf32 split of W1 (16384 elements)
__global__ void k_wsplit(const float* __restrict__ W1) {
    int i = blockIdx.x * blockDim.x + threadIdx.x;
    if (i < DD * DD) {
        float f = W1[i];
        uint32_t h = f2tf(f);
        g_wh[i] = h;
        g_wl[i] = f2tf(f - __uint_as_float(h));
    }
}

#define SX 136   // smem row stride in words (conflict-free fragment loads)

// ---------------- GEMM1: 3xtf32, double-buffered ----------------
__global__ void __launch_bounds__(256, 2)
k_gemm1_tc(const float* __restrict__ x, int n) {
    __shared__ uint32_t Xh[2][16 * SX], Xl[2][16 * SX];
    __shared__ uint32_t Wh[2][16 * SX], Wl[2][16 * SX];
    int tid = threadIdx.x;
    int wid = tid >> 5, lane = tid & 31;
    int gid = lane >> 2, tig = lane & 3;
    int warpM = wid & 3;          // 4 warps over M (32 rows)
    int warpN = wid >> 2;         // 2 warps over N (64 cols)
    int row0 = blockIdx.x * 128;

    float acc[2][8][4];
#pragma unroll
    for (int mt = 0; mt < 2; mt++)
#pragma unroll
        for (int nt = 0; nt < 8; nt++)
#pragma unroll
            for (int j = 0; j < 4; j++) acc[mt][nt][j] = 0.f;

    // stage loader: chunk kc (16 k-values) into buffer b
    auto load_chunk = [&](int kc, int b) {
        int kk = kc * 16;
        // X: 512 float4, convert + split + transpose to [k][row]
#pragma unroll
        for (int j = 0; j < 2; j++) {
            int idx = tid + j * 256;
            int r = idx >> 2, kq = idx & 3;
            float4 v = make_float4(0.f, 0.f, 0.f, 0.f);
            if (row0 + r < n)
                v = *(const float4*)(x + (size_t)(row0 + r) * DD + kk + kq * 4);
            float f[4] = {v.x, v.y, v.z, v.w};
#pragma unroll
            for (int i = 0; i < 4; i++) {
                uint32_t h = f2tf(f[i]);
                Xh[b][(kq * 4 + i) * SX + r] = h;
                Xl[b][(kq * 4 + i) * SX + r] = f2tf(f[i] - __uint_as_float(h));
            }
        }
        // W: pure copy from presplit globals (512 float4 per array)
#pragma unroll
        for (int j = 0; j < 2; j++) {
            int idx = tid + j * 256;
            int k = idx >> 5, c4 = idx & 31;
            *(uint4*)&Wh[b][k * SX + c4 * 4] =
                ((const uint4*)g_wh)[(size_t)(kk + k) * 32 + c4];
            *(uint4*)&Wl[b][k * SX + c4 * 4] =
                ((const uint4*)g_wl)[(size_t)(kk + k) * 32 + c4];
        }
    };

    load_chunk(0, 0);
    __syncthreads();

    for (int kc = 0; kc < 8; kc++) {
        int cur = kc & 1;
        if (kc < 7) load_chunk(kc + 1, cur ^ 1);
#pragma unroll
        for (int kb = 0; kb < 16; kb += 8) {
            uint32_t ah[2][4], al[2][4];
#pragma unroll
            for (int mt = 0; mt < 2; mt++) {
                int r = warpM * 32 + mt * 16 + gid;
                int kr0 = (kb + tig) * SX, kr4 = (kb + tig + 4) * SX;
                ah[mt][0] = Xh[cur][kr0 + r];     al[mt][0] = Xl[cur][kr0 + r];
                ah[mt][1] = Xh[cur][kr0 + r + 8]; al[mt][1] = Xl[cur][kr0 + r + 8];
                ah[mt][2] = Xh[cur][kr4 + r];     al[mt][2] = Xl[cur][kr4 + r];
                ah[mt][3] = Xh[cur][kr4 + r + 8]; al[mt][3] = Xl[cur][kr4 + r + 8];
            }
#pragma unroll
            for (int nt = 0; nt < 8; nt++) {
                int c = warpN * 64 + nt * 8 + gid;
                uint32_t bh[2], bl[2];
                bh[0] = Wh[cur][(kb + tig) * SX + c];
                bh[1] = Wh[cur][(kb + tig + 4) * SX + c];
                bl[0] = Wl[cur][(kb + tig) * SX + c];
                bl[1] = Wl[cur][(kb + tig + 4) * SX + c];
#pragma unroll
                for (int mt = 0; mt < 2; mt++) {
                    mma8(acc[mt][nt], ah[mt], bh);
                    mma8(acc[mt][nt], al[mt], bh);
                    mma8(acc[mt][nt], ah[mt], bl);
                }
            }
        }
        __syncthreads();
    }

    // epilogue
#pragma unroll
    for (int mt = 0; mt < 2; mt++) {
#pragma unroll
        for (int nt = 0; nt < 8; nt++) {
            int row = row0 + warpM * 32 + mt * 16 + gid;
            int col = warpN * 64 + nt * 8 + 2 * tig;
            if (row < n)
                *(float2*)&g_h1w[(size_t)row * DD + col] =
                    make_float2(acc[mt][nt][0], acc[mt][nt][1]);
            if (row + 8 < n)
                *(float2*)&g_h1w[(size_t)(row + 8) * DD + col] =
                    make_float2(acc[mt][nt][2], acc[mt][nt][3]);
        }
    }
}

// ------- Aggregate layer 1 + bias + relu + W2 projection (fused, warp/node) -------
__global__ void __launch_bounds__(256) k_agg1(const float* __restrict__ b1,
                                              const float* __restrict__ W2, int n) {
    int gw = (blockIdx.x * blockDim.x + threadIdx.x) >> 5;
    int lane = threadIdx.x & 31;
    if (gw >= n) return;
    float dn = g_dinv[gw];
    const float4* h = (const float4*)g_h1w;
    float4 own = h[(size_t)gw * 32 + lane];
    float s = dn * dn;
    float a0x = own.x * s, a0y = own.y * s, a0z = own.z * s, a0w = own.w * s;
    float a1x = 0.f, a1y = 0.f, a1z = 0.f, a1w = 0.f;
    int e0 = g_off[gw], e1 = g_off[gw + 1];
    int e = e0;
    for (; e + 1 < e1; e += 2) {
        int s0 = g_csr[e], s1 = g_csr[e + 1];
        float w0 = g_dinv[s0] * dn, w1 = g_dinv[s1] * dn;
        float4 v0 = h[(size_t)s0 * 32 + lane];
        float4 v1 = h[(size_t)s1 * 32 + lane];
        a0x += v0.x * w0; a0y += v0.y * w0; a0z += v0.z * w0; a0w += v0.w * w0;
        a1x += v1.x * w1; a1y += v1.y * w1; a1z += v1.z * w1; a1w += v1.w * w1;
    }
    if (e < e1) {
        int s0 = g_csr[e];
        float w0 = g_dinv[s0] * dn;
        float4 v0 = h[(size_t)s0 * 32 + lane];
        a0x += v0.x * w0; a0y += v0.y * w0; a0z += v0.z * w0; a0w += v0.w * w0;
    }
    float4 b = ((const float4*)b1)[lane];
    float ax = fmaxf(a0x + a1x + b.x, 0.f);
    float ay = fmaxf(a0y + a1y + b.y, 0.f);
    float az = fmaxf(a0z + a1z + b.z, 0.f);
    float aw = fmaxf(a0w + a1w + b.w, 0.f);
    // fused W2 projection (D_OUT = 2)
    const float2* w2 = (const float2*)W2;
    float2 w0 = w2[lane * 4 + 0], w1 = w2[lane * 4 + 1];
    float2 w2v = w2[lane * 4 + 2], w3 = w2[lane * 4 + 3];
    float o0 = ax * w0.x + ay * w1.x + az * w2v.x + aw * w3.x;
    float o1 = ax * w0.y + ay * w1.y + az * w2v.y + aw * w3.y;
#pragma unroll
    for (int d = 16; d; d >>= 1) {
        o0 += __shfl_xor_sync(0xffffffffu, o0, d);
        o1 += __shfl_xor_sync(0xffffffffu, o1, d);
    }
    if (lane == 0) g_h2w[gw] = make_float2(o0, o1);
}

// ---------------- Aggregate layer 2 (thread per node) ----------------
__global__ void k_agg2(const float* __restrict__ b2, float* __restrict__ out, int n) {
    int i = blockIdx.x * blockDim.x + threadIdx.x;
    if (i >= n) return;
    float dn = g_dinv[i];
    float2 hv = g_h2w[i];
    float o0 = hv.x * dn * dn + b2[0];
    float o1 = hv.y * dn * dn + b2[1];
    int e0 = g_off[i], e1 = g_off[i + 1];
    for (int e = e0; e < e1; e++) {
        int src = g_csr[e];
        float w = g_dinv[src] * dn;
        float2 v = g_h2w[src];
        o0 += v.x * w;
        o1 += v.y * w;
    }
    ((float2*)out)[i] = make_float2(o0, o1);
}

// ---------------- launch ----------------
extern "C" void kernel_launch(void* const* d_in, const int* in_sizes, int n_in,
                              void* d_out, int out_size) {
    const float* x  = (const float*)d_in[0];
    const void*  ei = d_in[1];
    const float* W1 = (const float*)d_in[2];
    const float* b1 = (const float*)d_in[3];
    const float* W2 = (const float*)d_in[4];
    const float* b2 = (const float*)d_in[5];
    float* out = (float*)d_out;

    const int n = in_sizes[0] / DD;       // 100000
    const int e = in_sizes[1] / 2;        // 600000
    const int nb = (n + SCAN_B - 1) / SCAN_B;

    k_init<<<(n + 255) / 256, 256>>>(n, (const unsigned*)ei);
    k_count<<<(e + 255) / 256, 256>>>(ei, e, n);
    k_scan1<<<nb, SCAN_B>>>(n);
    k_scan2<<<1, 128>>>(nb);
    k_scan3<<<nb, SCAN_B>>>(n, nb);
    k_fill<<<(e + 255) / 256, 256>>>(ei, e, n);
    k_wsplit<<<(DD * DD + 255) / 256, 256>>>(W1);
    k_gemm1_tc<<<(n + 127) / 128, 256>>>(x, n);
    k_agg1<<<(n + 7) / 8, 256>>>(b1, W2, n);
    k_agg2<<<(n + 255) / 256, 256>>>(b2, out, n);
}